// round 7
// baseline (speedup 1.0000x reference)
#include <cuda_runtime.h>
#include <cuda_fp16.h>
#include <cstdint>

// Problem constants
#define N_  10000
#define K_  32
#define M_  (N_ * K_)      // 320000
#define H_  128

// ---------------- scratch (device globals) ------------------------------------
__device__ float S_nh [N_ * H_];
__device__ float S_c  [N_ * H_];
__device__ float S_nf1[N_ * H_];
__device__ float S_eh [M_ * H_];
__device__ float S_nh2[M_ * H_];
__device__ float S_big[M_ * 384];
__device__ float S_w  [139264];          // transposed half weights

__device__ __forceinline__ float gelu_t(float x) {
    float x3 = x * x * x;
    return 0.5f * x * (1.f + tanhf(0.7978845608028654f * (x + 0.044715f * x3)));
}

// ---------------- f32 -> f16 copy ----------------------------------------------
__global__ void __launch_bounds__(256) half_kernel(
    const float* __restrict__ src, __half* __restrict__ dst, long n4)
{
    long i = (long)blockIdx.x * 256 + threadIdx.x;
    if (i >= n4) return;
    float4 v = ((const float4*)src)[i];
    ((__half2*)dst)[i * 2 + 0] = __floats2half2_rn(v.x, v.y);
    ((__half2*)dst)[i * 2 + 1] = __floats2half2_rn(v.z, v.w);
}

// ---------------- transpose + halve: src[K][N] -> dst[N][K] ----------------------
__global__ void __launch_bounds__(256) transpose_half(
    const float* __restrict__ src, __half* __restrict__ dst, int Krows, int Ncols)
{
    __shared__ float tile[32][33];
    int bx = blockIdx.x * 32, by = blockIdx.y * 32;
    int x = threadIdx.x & 31, y4 = threadIdx.x >> 5;
#pragma unroll
    for (int j = 0; j < 4; j++) {
        int r = by + y4 + j * 8;
        if (r < Krows && bx + x < Ncols)
            tile[y4 + j * 8][x] = src[(long)r * Ncols + bx + x];
    }
    __syncthreads();
#pragma unroll
    for (int j = 0; j < 4; j++) {
        int n = bx + y4 + j * 8;
        if (n < Ncols && by + x < Krows)
            dst[(long)n * Krows + by + x] = __float2half_rn(tile[x][y4 + j * 8]);
    }
}

// ---------------- layernorm (mode: 0 = f32 out, 1 = f16 out) ---------------------
__global__ void __launch_bounds__(128) ln_kernel(
    const float* __restrict__ x, const float* __restrict__ g,
    const float* __restrict__ b, void* __restrict__ y, int mode)
{
    long r = blockIdx.x;
    int t = threadIdx.x;
    float v = x[r * 128 + t];
    float s = v, s2 = v * v;
#pragma unroll
    for (int o = 16; o; o >>= 1) {
        s  += __shfl_xor_sync(0xffffffffu, s,  o);
        s2 += __shfl_xor_sync(0xffffffffu, s2, o);
    }
    __shared__ float red[8];
    int w = t >> 5;
    if ((t & 31) == 0) { red[w] = s; red[4 + w] = s2; }
    __syncthreads();
    s  = red[0] + red[1] + red[2] + red[3];
    s2 = red[4] + red[5] + red[6] + red[7];
    float mean = s * (1.f / 128.f);
    float var  = s2 * (1.f / 128.f) - mean * mean;
    float o = (v - mean) * rsqrtf(var + 1e-5f) * g[t] + b[t];
    if (mode) ((__half*)y)[r * 128 + t] = __float2half_rn(o);
    else      ((float*)y)[r * 128 + t] = o;
}

// ---------------- pipelined fp16 tensor GEMM (R5-proven mainloop) ----------------
// flags: bit0 gelu, bit1 f16 output.
#define BK 32
#define AS_BYTES 10240          // 128 rows * 40 halves * 2
#define WS_OFF   20480
#define GEMM_SMEM 40960

__device__ __forceinline__ void cp16(uint32_t dst, const void* src, int sz) {
    asm volatile("cp.async.cg.shared.global [%0], [%1], 16, %2;"
                 :: "r"(dst), "l"(src), "r"(sz));
}

__global__ void __launch_bounds__(256, 2) gemm_h(
    const __half* __restrict__ A,  int kdA,
    const __half* __restrict__ A2, int kdA2,
    const __half* __restrict__ Wt, const __half* __restrict__ Wt2,
    const float* __restrict__ bias,
    const int*   __restrict__ gather,
    const float* __restrict__ rowvec, int rowdiv,
    const float* __restrict__ resid,
    void* __restrict__ out,
    int M, int ncols, int flags)
{
    extern __shared__ __half smh[];
    uint32_t smb = (uint32_t)__cvta_generic_to_shared(smh);

    int tid  = threadIdx.x;
    int lane = tid & 31;
    int wid  = tid >> 5;
    int warp_m = wid >> 2;           // 0..1
    int warp_n = wid & 3;            // 0..3
    int qr = lane >> 2;              // 0..7
    int qc = lane & 3;               // 0..3
    int row0 = blockIdx.x * 128;
    int cb   = blockIdx.y * 128;

    int kc = tid & 3;
    int lrow0 = tid >> 2;
    long arow_[2]; int pr_[2];
#pragma unroll
    for (int i = 0; i < 2; i++) {
        int gr = row0 + lrow0 + 64 * i;
        pr_[i] = (gr < M) ? 16 : 0;
        arow_[i] = (gr < M) ? (gather ? (long)gather[gr] : (long)gr) : 0;
    }
    int t1 = kdA / BK;
    int nt = t1 + (A2 ? kdA2 / BK : 0);

#define ISSUE(T) do {                                                           \
        int _t = (T); int _p = (_t >= t1);                                      \
        const __half* _Ap = _p ? A2 : A;                                        \
        const __half* _Wp = _p ? Wt2 : Wt;                                      \
        int _kd = _p ? kdA2 : kdA;                                              \
        int _k0 = (_p ? _t - t1 : _t) * BK;                                     \
        uint32_t _ab = smb + (_t & 1) * AS_BYTES;                               \
        uint32_t _wb = smb + WS_OFF + (_t & 1) * AS_BYTES;                      \
        _Pragma("unroll")                                                       \
        for (int _i = 0; _i < 2; _i++)                                          \
            cp16(_ab + (lrow0 + 64 * _i) * 80 + kc * 16,                        \
                 _Ap + arow_[_i] * _kd + _k0 + kc * 8, pr_[_i]);                \
        _Pragma("unroll")                                                       \
        for (int _i = 0; _i < 2; _i++)                                          \
            cp16(_wb + (lrow0 + 64 * _i) * 80 + kc * 16,                        \
                 _Wp + (long)(cb + lrow0 + 64 * _i) * _kd + _k0 + kc * 8, 16);  \
        asm volatile("cp.async.commit_group;" ::: "memory");                    \
    } while (0)

    float acc[4][4][4];
#pragma unroll
    for (int i = 0; i < 4; i++)
#pragma unroll
        for (int j = 0; j < 4; j++)
#pragma unroll
            for (int c = 0; c < 4; c++) acc[i][j][c] = 0.f;

    ISSUE(0);
    for (int t = 0; t < nt; t++) {
        int cur = t & 1;
        if (t + 1 < nt) {
            ISSUE(t + 1);
            asm volatile("cp.async.wait_group 1;" ::: "memory");
        } else {
            asm volatile("cp.async.wait_group 0;" ::: "memory");
        }
        __syncthreads();

        const __half* Asf = smh + cur * (AS_BYTES / 2) + (warp_m * 64) * 40;
        const __half* Wsf = smh + (WS_OFF / 2) + cur * (AS_BYTES / 2) + (warp_n * 32) * 40;
#pragma unroll
        for (int ks = 0; ks < 2; ks++) {
            int k16 = ks * 16;
            uint32_t af[4][4];
#pragma unroll
            for (int mt = 0; mt < 4; mt++) {
                const __half* p = Asf + (mt * 16 + qr) * 40 + k16 + qc * 2;
                af[mt][0] = *(const uint32_t*)(p);
                af[mt][1] = *(const uint32_t*)(p + 8 * 40);
                af[mt][2] = *(const uint32_t*)(p + 8);
                af[mt][3] = *(const uint32_t*)(p + 8 * 40 + 8);
            }
            uint32_t bf[4][2];
#pragma unroll
            for (int nt2 = 0; nt2 < 4; nt2++) {
                const __half* p = Wsf + (nt2 * 8 + qr) * 40 + k16 + qc * 2;
                bf[nt2][0] = *(const uint32_t*)(p);
                bf[nt2][1] = *(const uint32_t*)(p + 8);
            }
#pragma unroll
            for (int mt = 0; mt < 4; mt++)
#pragma unroll
                for (int nt2 = 0; nt2 < 4; nt2++) {
                    asm volatile(
                        "mma.sync.aligned.m16n8k16.row.col.f32.f16.f16.f32 "
                        "{%0,%1,%2,%3}, {%4,%5,%6,%7}, {%8,%9}, {%0,%1,%2,%3};"
                        : "+f"(acc[mt][nt2][0]), "+f"(acc[mt][nt2][1]),
                          "+f"(acc[mt][nt2][2]), "+f"(acc[mt][nt2][3])
                        : "r"(af[mt][0]), "r"(af[mt][1]),
                          "r"(af[mt][2]), "r"(af[mt][3]),
                          "r"(bf[nt2][0]), "r"(bf[nt2][1]));
                }
        }
        __syncthreads();
    }
#undef ISSUE

    int gelu = flags & 1, halfout = flags & 2;
#pragma unroll
    for (int mt = 0; mt < 4; mt++) {
#pragma unroll
        for (int hh = 0; hh < 2; hh++) {
            int gr = row0 + warp_m * 64 + mt * 16 + hh * 8 + qr;
            if (gr >= M) continue;
            const float* rv = rowvec ? rowvec + (long)(gr / rowdiv) * 128 : nullptr;
#pragma unroll
            for (int nt2 = 0; nt2 < 4; nt2++) {
                int c = cb + warp_n * 32 + nt2 * 8 + qc * 2;
                float v0 = acc[mt][nt2][hh * 2 + 0];
                float v1 = acc[mt][nt2][hh * 2 + 1];
                if (bias) { v0 += bias[c];  v1 += bias[c + 1]; }
                if (rv)   { v0 += rv[c];    v1 += rv[c + 1]; }
                if (gelu) { v0 = gelu_t(v0); v1 = gelu_t(v1); }
                long oidx = (long)gr * ncols + c;
                if (halfout) {
                    *(__half2*)((__half*)out + oidx) = __floats2half2_rn(v0, v1);
                } else {
                    if (resid) {
                        float2 r2 = *(const float2*)(resid + oidx);
                        v0 += r2.x; v1 += r2.y;
                    }
                    *(float2*)((float*)out + oidx) = make_float2(v0, v1);
                }
            }
        }
    }
}

// ---------------- attention core: f16 qkv in, f16 ctx out ------------------------
#define ATTN_SMEM (3 * 4096 * 4)
__global__ void __launch_bounds__(256) attn_kernel(
    const __half* __restrict__ qkv,
    const int*   __restrict__ num_valid,
    __half* __restrict__ ctx_out)
{
    extern __shared__ float sm[];
    float* sQ = sm;
    float* sK = sQ + 4096;
    float* sV = sK + 4096;
    int n = blockIdx.x;
    int tid = threadIdx.x;

    const __half* src = qkv + (long)n * 32 * 384;
#pragma unroll
    for (int i = 0; i < 6; i++) {
        int lin = tid + i * 256;        // 0..1535 (8-half chunks)
        int j = lin / 48, c8 = lin % 48;
        uint4 raw = *(const uint4*)(src + j * 384 + c8 * 8);
        float2 f0 = __half22float2(*(__half2*)&raw.x);
        float2 f1 = __half22float2(*(((__half2*)&raw.x) + 1));
        float2 f2 = __half22float2(*(__half2*)&raw.z);
        float2 f3 = __half22float2(*(((__half2*)&raw.z) + 1));
        float* dst = (c8 < 16) ? &sQ[j * 128 + c8 * 8]
                   : (c8 < 32) ? &sK[j * 128 + (c8 - 16) * 8]
                               : &sV[j * 128 + (c8 - 32) * 8];
        dst[0] = f0.x; dst[1] = f0.y; dst[2] = f1.x; dst[3] = f1.y;
        dst[4] = f2.x; dst[5] = f2.y; dst[6] = f3.x; dst[7] = f3.y;
    }
    __syncthreads();

    int nv = num_valid[n];
    int head = tid >> 5, q = tid & 31;
    int hc = head * 16;
    float qv[16];
#pragma unroll
    for (int d = 0; d < 4; d++)
        *(float4*)&qv[d * 4] = *(const float4*)&sQ[q * 128 + hc + d * 4];
    float s[32];
#pragma unroll
    for (int j = 0; j < 32; j++) {
        float a = 0.f;
#pragma unroll
        for (int d = 0; d < 4; d++) {
            float4 kv = *(const float4*)&sK[j * 128 + hc + d * 4];
            a += qv[d*4]*kv.x + qv[d*4+1]*kv.y + qv[d*4+2]*kv.z + qv[d*4+3]*kv.w;
        }
        s[j] = a * 0.25f;
    }
    float m = -1e30f;
#pragma unroll
    for (int j = 0; j < 32; j++) if (j < nv && s[j] > m) m = s[j];
    float sum = 0.f;
#pragma unroll
    for (int j = 0; j < 32; j++) {
        float p = (j < nv) ? __expf(s[j] - m) : 0.f;
        s[j] = p; sum += p;
    }
    float inv = 1.f / sum;
    float ctx[16];
#pragma unroll
    for (int d = 0; d < 16; d++) ctx[d] = 0.f;
#pragma unroll
    for (int j = 0; j < 32; j++) {
        float p = s[j] * inv;
#pragma unroll
        for (int d = 0; d < 4; d++) {
            float4 vv = *(const float4*)&sV[j * 128 + hc + d * 4];
            ctx[d*4]   += p * vv.x; ctx[d*4+1] += p * vv.y;
            ctx[d*4+2] += p * vv.z; ctx[d*4+3] += p * vv.w;
        }
    }
    uint4 o0, o1;
    __half2 h;
    h = __floats2half2_rn(ctx[0],  ctx[1]);  o0.x = *(uint32_t*)&h;
    h = __floats2half2_rn(ctx[2],  ctx[3]);  o0.y = *(uint32_t*)&h;
    h = __floats2half2_rn(ctx[4],  ctx[5]);  o0.z = *(uint32_t*)&h;
    h = __floats2half2_rn(ctx[6],  ctx[7]);  o0.w = *(uint32_t*)&h;
    h = __floats2half2_rn(ctx[8],  ctx[9]);  o1.x = *(uint32_t*)&h;
    h = __floats2half2_rn(ctx[10], ctx[11]); o1.y = *(uint32_t*)&h;
    h = __floats2half2_rn(ctx[12], ctx[13]); o1.z = *(uint32_t*)&h;
    h = __floats2half2_rn(ctx[14], ctx[15]); o1.w = *(uint32_t*)&h;
    __half* dst = ctx_out + (long)n * 4096 + q * 128 + hc;
    *(uint4*)dst = o0;
    *(uint4*)(dst + 8) = o1;
}

// ---------------- masked aggregation from residual difference --------------------
// node1[n] = sum_{k<nv} (out_edge[n,k] - edge_feat[n,k]) + node_feat[n]
__global__ void __launch_bounds__(128) agg_kernel(
    const float* __restrict__ out_edge, const float* __restrict__ edge_feat,
    const float* __restrict__ node_feat,
    const int* __restrict__ num_valid, float* __restrict__ node1)
{
    int n = blockIdx.x, t = threadIdx.x;
    int nv = num_valid[n];
    long base = (long)n * 32 * 128 + t;
    float s = 0.f;
    for (int k = 0; k < nv; k++)
        s += out_edge[base + k * 128] - edge_feat[base + k * 128];
    node1[(long)n * 128 + t] = s + node_feat[(long)n * 128 + t];
}

// ---------------- driver -----------------------------------------------------------
static void launch_gemm(const __half* A, int kdA, const __half* A2, int kdA2,
                        const __half* Wt, const __half* Wt2, const float* bias,
                        const int* gather, const float* rowvec, int rowdiv,
                        const float* resid, void* out,
                        int M, int ncols, int flags)
{
    dim3 g((M + 127) / 128, ncols / 128);
    gemm_h<<<g, 256, GEMM_SMEM>>>(A, kdA, A2, kdA2, Wt, Wt2, bias, gather,
                                  rowvec, rowdiv, resid, out, M, ncols, flags);
}
static void launch_T(const float* src, __half* dst, int K, int N) {
    dim3 g((N + 31) / 32, (K + 31) / 32);
    transpose_half<<<g, 256>>>(src, dst, K, N);
}
static void launch_half(const float* src, __half* dst, long n) {
    long n4 = n / 4;
    half_kernel<<<(unsigned)((n4 + 255) / 256), 256>>>(src, dst, n4);
}

extern "C" void kernel_launch(void* const* d_in, const int* in_sizes, int n_in,
                              void* d_out, int out_size)
{
    const float* node_features = (const float*)d_in[0];
    const float* edge_features = (const float*)d_in[1];
    const float* edge_attr     = (const float*)d_in[2];
    const int*   neighbor_list = (const int*)d_in[3];
    const int*   num_valid     = (const int*)d_in[4];
    const float* W_edge = (const float*)d_in[5];
    const float* b_edge = (const float*)d_in[6];
    const float* W_node = (const float*)d_in[7];
    const float* b_node = (const float*)d_in[8];
    const float* W_msg  = (const float*)d_in[9];
    const float* b_msg  = (const float*)d_in[10];
    const float* W_qkv  = (const float*)d_in[11];
    const float* b_qkv  = (const float*)d_in[12];
    const float* W_out  = (const float*)d_in[13];
    const float* b_out  = (const float*)d_in[14];
    const float* g_attn = (const float*)d_in[15];
    const float* be_attn= (const float*)d_in[16];
    const float* g_fn   = (const float*)d_in[17];
    const float* be_fn  = (const float*)d_in[18];
    const float* g_fe   = (const float*)d_in[19];
    const float* be_fe  = (const float*)d_in[20];
    const float* Wn1 = (const float*)d_in[21];
    const float* bn1 = (const float*)d_in[22];
    const float* Wn2 = (const float*)d_in[23];
    const float* bn2 = (const float*)d_in[24];
    const float* We1 = (const float*)d_in[25];
    const float* be1 = (const float*)d_in[26];
    const float* We2 = (const float*)d_in[27];
    const float* be2 = (const float*)d_in[28];

    float *s_nh, *s_c, *s_nf1, *s_eh, *s_nh2, *s_big, *s_w;
    cudaGetSymbolAddress((void**)&s_nh,  S_nh);
    cudaGetSymbolAddress((void**)&s_c,   S_c);
    cudaGetSymbolAddress((void**)&s_nf1, S_nf1);
    cudaGetSymbolAddress((void**)&s_eh,  S_eh);
    cudaGetSymbolAddress((void**)&s_nh2, S_nh2);
    cudaGetSymbolAddress((void**)&s_big, S_big);
    cudaGetSymbolAddress((void**)&s_w,   S_w);

    cudaFuncSetAttribute(attn_kernel, cudaFuncAttributeMaxDynamicSharedMemorySize, ATTN_SMEM);

    float* out_node = (float*)d_out;
    float* out_edge = out_node + (long)N_ * H_;

    __half* h_nh  = (__half*)s_nh;
    __half* h_ea  = (__half*)s_big;
    __half* h_eh  = (__half*)s_eh;
    __half* h_nh2 = (__half*)s_nh2;
    __half* h_c   = (__half*)s_c;
    __half* h_qkv = (__half*)s_big;
    __half* h_hid = (__half*)s_big;

    __half* wbase = (__half*)s_w;
    __half* tW_edge  = wbase;
    __half* tW_nodeC = wbase + 16384;
    __half* tW_nodeN = wbase + 32768;
    __half* tW_msgE  = wbase + 49152;
    __half* tW_msgN  = wbase + 65536;
    __half* tW_qkv   = wbase + 81920;
    __half* tW_out   = wbase + 131072;
    __half* tWn1     = wbase + 147456;
    __half* tWn2     = wbase + 180224;
    __half* tWe1     = wbase + 212992;
    __half* tWe2     = wbase + 245760;

    // 0) transpose+halve weights; halve edge_attr
    launch_T(W_edge,            tW_edge,  128, 128);
    launch_T(W_node,            tW_nodeC, 128, 128);
    launch_T(W_node + 128*128,  tW_nodeN, 128, 128);
    launch_T(W_msg,             tW_msgE,  128, 128);
    launch_T(W_msg + 128*128,   tW_msgN,  128, 128);
    launch_T(W_qkv,             tW_qkv,   128, 384);
    launch_T(W_out,             tW_out,   128, 128);
    launch_T(Wn1,               tWn1,     128, 256);
    launch_T(Wn2,               tWn2,     256, 128);
    launch_T(We1,               tWe1,     128, 256);
    launch_T(We2,               tWe2,     256, 128);
    launch_half(edge_attr, h_ea, (long)M_ * 128);

    // 1) node_hidden = LN(node_features) -> f16
    ln_kernel<<<N_, 128>>>(node_features, g_attn, be_attn, h_nh, 1);
    // 2) edge_hidden = gelu(edge_attr @ W_edge + b) -> f16
    launch_gemm(h_ea, 128, nullptr, 0, tW_edge, nullptr, b_edge,
                nullptr, nullptr, 1, nullptr, h_eh, M_, 128, 3);
    // 3a) center proj -> f32
    launch_gemm(h_nh, 128, nullptr, 0, tW_nodeC, nullptr, nullptr,
                nullptr, nullptr, 1, nullptr, s_c, N_, 128, 0);
    // 3b) node_hid = gelu(nbr@WnodeN + center + b) -> f16 (gathered)
    launch_gemm(h_nh, 128, nullptr, 0, tW_nodeN, nullptr, b_node,
                neighbor_list, s_c, K_, nullptr, h_nh2, M_, 128, 3);
    // 4) msg = gelu(eh@WmE + nh@WmN + b) -> f16 (in-place)
    launch_gemm(h_eh, 128, h_nh2, 128, tW_msgE, tW_msgN, b_msg,
                nullptr, nullptr, 1, nullptr, h_eh, M_, 128, 3);
    // 5) qkv = msg @ W_qkv + b -> f16
    launch_gemm(h_eh, 128, nullptr, 0, tW_qkv, nullptr, b_qkv,
                nullptr, nullptr, 1, nullptr, h_qkv, M_, 384, 2);
    // 6a) attention core -> ctx f16
    attn_kernel<<<N_, 256, ATTN_SMEM>>>(h_qkv, num_valid, h_nh2);
    // 6b) out-projection + edge residual
    launch_gemm(h_nh2, 128, nullptr, 0, tW_out, nullptr, b_out,
                nullptr, nullptr, 1, edge_features, out_edge, M_, 128, 0);
    // 6c) masked aggregation from residual difference + node residual
    agg_kernel<<<N_, 128>>>(out_edge, edge_features, node_features, num_valid, s_nf1);
    // 7) node FFN
    ln_kernel<<<N_, 128>>>(s_nf1, g_fn, be_fn, h_c, 1);
    launch_gemm(h_c, 128, nullptr, 0, tWn1, nullptr, bn1,
                nullptr, nullptr, 1, nullptr, h_hid, N_, 256, 3);
    launch_gemm(h_hid, 256, nullptr, 0, tWn2, nullptr, bn2,
                nullptr, nullptr, 1, s_nf1, out_node, N_, 128, 0);
    // 8) edge FFN
    ln_kernel<<<M_, 128>>>(out_edge, g_fe, be_fe, h_nh2, 1);
    launch_gemm(h_nh2, 128, nullptr, 0, tWe1, nullptr, be1,
                nullptr, nullptr, 1, nullptr, h_hid, M_, 256, 3);
    launch_gemm(h_hid, 256, nullptr, 0, tWe2, nullptr, be2,
                nullptr, nullptr, 1, out_edge, out_edge, M_, 128, 0);
}

// round 8
// speedup vs baseline: 1.5465x; 1.5465x over previous
#include <cuda_runtime.h>
#include <cuda_fp16.h>
#include <cstdint>

// Problem constants
#define N_  10000
#define K_  32
#define M_  (N_ * K_)      // 320000
#define H_  128

// ---------------- scratch (device globals) ------------------------------------
__device__ float S_nh [N_ * H_];
__device__ float S_c  [N_ * H_];
__device__ float S_nf1[N_ * H_];
__device__ float S_eh [M_ * H_];
__device__ float S_nh2[M_ * H_];
__device__ float S_big[M_ * 384];
__device__ float S_w  [139264];          // transposed half weights

__device__ __forceinline__ float gelu_t(float x) {
    float x3 = x * x * x;
    return 0.5f * x * (1.f + tanhf(0.7978845608028654f * (x + 0.044715f * x3)));
}

// ---------------- f32 -> f16 copy ----------------------------------------------
__global__ void __launch_bounds__(256) half_kernel(
    const float* __restrict__ src, __half* __restrict__ dst, long n4)
{
    long i = (long)blockIdx.x * 256 + threadIdx.x;
    if (i >= n4) return;
    float4 v = ((const float4*)src)[i];
    ((__half2*)dst)[i * 2 + 0] = __floats2half2_rn(v.x, v.y);
    ((__half2*)dst)[i * 2 + 1] = __floats2half2_rn(v.z, v.w);
}

// ---------------- transpose + halve: src[K][N] -> dst[N][K] ----------------------
__global__ void __launch_bounds__(256) transpose_half(
    const float* __restrict__ src, __half* __restrict__ dst, int Krows, int Ncols)
{
    __shared__ float tile[32][33];
    int bx = blockIdx.x * 32, by = blockIdx.y * 32;
    int x = threadIdx.x & 31, y4 = threadIdx.x >> 5;
#pragma unroll
    for (int j = 0; j < 4; j++) {
        int r = by + y4 + j * 8;
        if (r < Krows && bx + x < Ncols)
            tile[y4 + j * 8][x] = src[(long)r * Ncols + bx + x];
    }
    __syncthreads();
#pragma unroll
    for (int j = 0; j < 4; j++) {
        int n = bx + y4 + j * 8;
        if (n < Ncols && by + x < Krows)
            dst[(long)n * Krows + by + x] = __float2half_rn(tile[x][y4 + j * 8]);
    }
}

// ---------------- layernorm: warp-per-row (mode: 0=f32 out, 1=f16 out) -----------
__global__ void __launch_bounds__(256) ln_kernel(
    const float* __restrict__ x, const float* __restrict__ g,
    const float* __restrict__ b, void* __restrict__ y, int mode, int nrows)
{
    int row  = blockIdx.x * 8 + (threadIdx.x >> 5);
    if (row >= nrows) return;
    int lane = threadIdx.x & 31;
    long base = (long)row * 128 + lane * 4;
    float4 v = *(const float4*)(x + base);
    float s  = v.x + v.y + v.z + v.w;
    float s2 = v.x*v.x + v.y*v.y + v.z*v.z + v.w*v.w;
#pragma unroll
    for (int o = 16; o; o >>= 1) {
        s  += __shfl_xor_sync(0xffffffffu, s,  o);
        s2 += __shfl_xor_sync(0xffffffffu, s2, o);
    }
    float mean = s * (1.f / 128.f);
    float var  = s2 * (1.f / 128.f) - mean * mean;
    float r = rsqrtf(var + 1e-5f);
    float4 gv = *(const float4*)(g + lane * 4);
    float4 bv = *(const float4*)(b + lane * 4);
    float o0 = (v.x - mean) * r * gv.x + bv.x;
    float o1 = (v.y - mean) * r * gv.y + bv.y;
    float o2 = (v.z - mean) * r * gv.z + bv.z;
    float o3 = (v.w - mean) * r * gv.w + bv.w;
    if (mode) {
        __half2 h0 = __floats2half2_rn(o0, o1);
        __half2 h1 = __floats2half2_rn(o2, o3);
        uint2 pk = make_uint2(*(uint32_t*)&h0, *(uint32_t*)&h1);
        *(uint2*)((__half*)y + base) = pk;
    } else {
        *(float4*)((float*)y + base) = make_float4(o0, o1, o2, o3);
    }
}

// ---------------- pipelined fp16 tensor GEMM (R5-proven mainloop) ----------------
// flags: bit0 gelu, bit1 f16 output. out2 (f32, optional): pre-residual copy.
#define BK 32
#define AS_BYTES 10240          // 128 rows * 40 halves * 2
#define WS_OFF   20480
#define GEMM_SMEM 40960

__device__ __forceinline__ void cp16(uint32_t dst, const void* src, int sz) {
    asm volatile("cp.async.cg.shared.global [%0], [%1], 16, %2;"
                 :: "r"(dst), "l"(src), "r"(sz));
}

__global__ void __launch_bounds__(256, 2) gemm_h(
    const __half* __restrict__ A,  int kdA,
    const __half* __restrict__ A2, int kdA2,
    const __half* __restrict__ Wt, const __half* __restrict__ Wt2,
    const float* __restrict__ bias,
    const int*   __restrict__ gather,
    const float* __restrict__ rowvec, int rowdiv,
    const float* __restrict__ resid,
    void* __restrict__ out, float* __restrict__ out2,
    int M, int ncols, int flags)
{
    extern __shared__ __half smh[];
    uint32_t smb = (uint32_t)__cvta_generic_to_shared(smh);

    int tid  = threadIdx.x;
    int lane = tid & 31;
    int wid  = tid >> 5;
    int warp_m = wid >> 2;           // 0..1
    int warp_n = wid & 3;            // 0..3
    int qr = lane >> 2;              // 0..7
    int qc = lane & 3;               // 0..3
    int row0 = blockIdx.x * 128;
    int cb   = blockIdx.y * 128;

    int kc = tid & 3;
    int lrow0 = tid >> 2;
    long arow_[2]; int pr_[2];
#pragma unroll
    for (int i = 0; i < 2; i++) {
        int gr = row0 + lrow0 + 64 * i;
        pr_[i] = (gr < M) ? 16 : 0;
        arow_[i] = (gr < M) ? (gather ? (long)gather[gr] : (long)gr) : 0;
    }
    int t1 = kdA / BK;
    int nt = t1 + (A2 ? kdA2 / BK : 0);

#define ISSUE(T) do {                                                           \
        int _t = (T); int _p = (_t >= t1);                                      \
        const __half* _Ap = _p ? A2 : A;                                        \
        const __half* _Wp = _p ? Wt2 : Wt;                                      \
        int _kd = _p ? kdA2 : kdA;                                              \
        int _k0 = (_p ? _t - t1 : _t) * BK;                                     \
        uint32_t _ab = smb + (_t & 1) * AS_BYTES;                               \
        uint32_t _wb = smb + WS_OFF + (_t & 1) * AS_BYTES;                      \
        _Pragma("unroll")                                                       \
        for (int _i = 0; _i < 2; _i++)                                          \
            cp16(_ab + (lrow0 + 64 * _i) * 80 + kc * 16,                        \
                 _Ap + arow_[_i] * _kd + _k0 + kc * 8, pr_[_i]);                \
        _Pragma("unroll")                                                       \
        for (int _i = 0; _i < 2; _i++)                                          \
            cp16(_wb + (lrow0 + 64 * _i) * 80 + kc * 16,                        \
                 _Wp + (long)(cb + lrow0 + 64 * _i) * _kd + _k0 + kc * 8, 16);  \
        asm volatile("cp.async.commit_group;" ::: "memory");                    \
    } while (0)

    float acc[4][4][4];
#pragma unroll
    for (int i = 0; i < 4; i++)
#pragma unroll
        for (int j = 0; j < 4; j++)
#pragma unroll
            for (int c = 0; c < 4; c++) acc[i][j][c] = 0.f;

    ISSUE(0);
    for (int t = 0; t < nt; t++) {
        int cur = t & 1;
        if (t + 1 < nt) {
            ISSUE(t + 1);
            asm volatile("cp.async.wait_group 1;" ::: "memory");
        } else {
            asm volatile("cp.async.wait_group 0;" ::: "memory");
        }
        __syncthreads();

        const __half* Asf = smh + cur * (AS_BYTES / 2) + (warp_m * 64) * 40;
        const __half* Wsf = smh + (WS_OFF / 2) + cur * (AS_BYTES / 2) + (warp_n * 32) * 40;
#pragma unroll
        for (int ks = 0; ks < 2; ks++) {
            int k16 = ks * 16;
            uint32_t af[4][4];
#pragma unroll
            for (int mt = 0; mt < 4; mt++) {
                const __half* p = Asf + (mt * 16 + qr) * 40 + k16 + qc * 2;
                af[mt][0] = *(const uint32_t*)(p);
                af[mt][1] = *(const uint32_t*)(p + 8 * 40);
                af[mt][2] = *(const uint32_t*)(p + 8);
                af[mt][3] = *(const uint32_t*)(p + 8 * 40 + 8);
            }
            uint32_t bf[4][2];
#pragma unroll
            for (int nt2 = 0; nt2 < 4; nt2++) {
                const __half* p = Wsf + (nt2 * 8 + qr) * 40 + k16 + qc * 2;
                bf[nt2][0] = *(const uint32_t*)(p);
                bf[nt2][1] = *(const uint32_t*)(p + 8);
            }
#pragma unroll
            for (int mt = 0; mt < 4; mt++)
#pragma unroll
                for (int nt2 = 0; nt2 < 4; nt2++) {
                    asm volatile(
                        "mma.sync.aligned.m16n8k16.row.col.f32.f16.f16.f32 "
                        "{%0,%1,%2,%3}, {%4,%5,%6,%7}, {%8,%9}, {%0,%1,%2,%3};"
                        : "+f"(acc[mt][nt2][0]), "+f"(acc[mt][nt2][1]),
                          "+f"(acc[mt][nt2][2]), "+f"(acc[mt][nt2][3])
                        : "r"(af[mt][0]), "r"(af[mt][1]),
                          "r"(af[mt][2]), "r"(af[mt][3]),
                          "r"(bf[nt2][0]), "r"(bf[nt2][1]));
                }
        }
        __syncthreads();
    }
#undef ISSUE

    int gelu = flags & 1, halfout = flags & 2;
#pragma unroll
    for (int mt = 0; mt < 4; mt++) {
#pragma unroll
        for (int hh = 0; hh < 2; hh++) {
            int gr = row0 + warp_m * 64 + mt * 16 + hh * 8 + qr;
            if (gr >= M) continue;
            const float* rv = rowvec ? rowvec + (long)(gr / rowdiv) * 128 : nullptr;
#pragma unroll
            for (int nt2 = 0; nt2 < 4; nt2++) {
                int c = cb + warp_n * 32 + nt2 * 8 + qc * 2;
                float v0 = acc[mt][nt2][hh * 2 + 0];
                float v1 = acc[mt][nt2][hh * 2 + 1];
                if (bias) { v0 += bias[c];  v1 += bias[c + 1]; }
                if (rv)   { v0 += rv[c];    v1 += rv[c + 1]; }
                if (gelu) { v0 = gelu_t(v0); v1 = gelu_t(v1); }
                long oidx = (long)gr * ncols + c;
                if (halfout) {
                    *(__half2*)((__half*)out + oidx) = __floats2half2_rn(v0, v1);
                } else {
                    if (out2) *(float2*)(out2 + oidx) = make_float2(v0, v1);
                    if (resid) {
                        float2 r2 = *(const float2*)(resid + oidx);
                        v0 += r2.x; v1 += r2.y;
                    }
                    *(float2*)((float*)out + oidx) = make_float2(v0, v1);
                }
            }
        }
    }
}

// ---------------- attention core: f16 qkv in, f16 ctx out ------------------------
#define ATTN_SMEM (3 * 4096 * 4)
__global__ void __launch_bounds__(256) attn_kernel(
    const __half* __restrict__ qkv,
    const int*   __restrict__ num_valid,
    __half* __restrict__ ctx_out)
{
    extern __shared__ float sm[];
    float* sQ = sm;
    float* sK = sQ + 4096;
    float* sV = sK + 4096;
    int n = blockIdx.x;
    int tid = threadIdx.x;

    const __half* src = qkv + (long)n * 32 * 384;
#pragma unroll
    for (int i = 0; i < 6; i++) {
        int lin = tid + i * 256;        // 0..1535 (8-half chunks)
        int j = lin / 48, c8 = lin % 48;
        uint4 raw = *(const uint4*)(src + j * 384 + c8 * 8);
        float2 f0 = __half22float2(*(__half2*)&raw.x);
        float2 f1 = __half22float2(*(((__half2*)&raw.x) + 1));
        float2 f2 = __half22float2(*(__half2*)&raw.z);
        float2 f3 = __half22float2(*(((__half2*)&raw.z) + 1));
        float* dst = (c8 < 16) ? &sQ[j * 128 + c8 * 8]
                   : (c8 < 32) ? &sK[j * 128 + (c8 - 16) * 8]
                               : &sV[j * 128 + (c8 - 32) * 8];
        dst[0] = f0.x; dst[1] = f0.y; dst[2] = f1.x; dst[3] = f1.y;
        dst[4] = f2.x; dst[5] = f2.y; dst[6] = f3.x; dst[7] = f3.y;
    }
    __syncthreads();

    int nv = num_valid[n];
    int head = tid >> 5, q = tid & 31;
    int hc = head * 16;
    float qv[16];
#pragma unroll
    for (int d = 0; d < 4; d++)
        *(float4*)&qv[d * 4] = *(const float4*)&sQ[q * 128 + hc + d * 4];
    float s[32];
#pragma unroll
    for (int j = 0; j < 32; j++) {
        float a = 0.f;
#pragma unroll
        for (int d = 0; d < 4; d++) {
            float4 kv = *(const float4*)&sK[j * 128 + hc + d * 4];
            a += qv[d*4]*kv.x + qv[d*4+1]*kv.y + qv[d*4+2]*kv.z + qv[d*4+3]*kv.w;
        }
        s[j] = a * 0.25f;
    }
    float m = -1e30f;
#pragma unroll
    for (int j = 0; j < 32; j++) if (j < nv && s[j] > m) m = s[j];
    float sum = 0.f;
#pragma unroll
    for (int j = 0; j < 32; j++) {
        float p = (j < nv) ? __expf(s[j] - m) : 0.f;
        s[j] = p; sum += p;
    }
    float inv = 1.f / sum;
    float ctx[16];
#pragma unroll
    for (int d = 0; d < 16; d++) ctx[d] = 0.f;
#pragma unroll
    for (int j = 0; j < 32; j++) {
        float p = s[j] * inv;
#pragma unroll
        for (int d = 0; d < 4; d++) {
            float4 vv = *(const float4*)&sV[j * 128 + hc + d * 4];
            ctx[d*4]   += p * vv.x; ctx[d*4+1] += p * vv.y;
            ctx[d*4+2] += p * vv.z; ctx[d*4+3] += p * vv.w;
        }
    }
    uint4 o0, o1;
    __half2 h;
    h = __floats2half2_rn(ctx[0],  ctx[1]);  o0.x = *(uint32_t*)&h;
    h = __floats2half2_rn(ctx[2],  ctx[3]);  o0.y = *(uint32_t*)&h;
    h = __floats2half2_rn(ctx[4],  ctx[5]);  o0.z = *(uint32_t*)&h;
    h = __floats2half2_rn(ctx[6],  ctx[7]);  o0.w = *(uint32_t*)&h;
    h = __floats2half2_rn(ctx[8],  ctx[9]);  o1.x = *(uint32_t*)&h;
    h = __floats2half2_rn(ctx[10], ctx[11]); o1.y = *(uint32_t*)&h;
    h = __floats2half2_rn(ctx[12], ctx[13]); o1.z = *(uint32_t*)&h;
    h = __floats2half2_rn(ctx[14], ctx[15]); o1.w = *(uint32_t*)&h;
    __half* dst = ctx_out + (long)n * 4096 + q * 128 + hc;
    *(uint4*)dst = o0;
    *(uint4*)(dst + 8) = o1;
}

// ---------------- masked scatter-aggregate (R5 version) ---------------------------
__global__ void __launch_bounds__(128) agg_kernel(
    const float* __restrict__ edge_out, const float* __restrict__ node_feat,
    const int* __restrict__ num_valid, float* __restrict__ node1)
{
    int n = blockIdx.x, t = threadIdx.x;
    int nv = num_valid[n];
    const float* p = edge_out + (long)n * 32 * 128 + t;
    float s = 0.f;
    for (int k = 0; k < nv; k++) s += p[k * 128];
    node1[(long)n * 128 + t] = s + node_feat[(long)n * 128 + t];
}

// ---------------- driver -----------------------------------------------------------
static void launch_gemm(const __half* A, int kdA, const __half* A2, int kdA2,
                        const __half* Wt, const __half* Wt2, const float* bias,
                        const int* gather, const float* rowvec, int rowdiv,
                        const float* resid, void* out, float* out2,
                        int M, int ncols, int flags)
{
    dim3 g((M + 127) / 128, ncols / 128);
    gemm_h<<<g, 256, GEMM_SMEM>>>(A, kdA, A2, kdA2, Wt, Wt2, bias, gather,
                                  rowvec, rowdiv, resid, out, out2, M, ncols, flags);
}
static void launch_T(const float* src, __half* dst, int K, int N) {
    dim3 g((N + 31) / 32, (K + 31) / 32);
    transpose_half<<<g, 256>>>(src, dst, K, N);
}
static void launch_half(const float* src, __half* dst, long n) {
    long n4 = n / 4;
    half_kernel<<<(unsigned)((n4 + 255) / 256), 256>>>(src, dst, n4);
}
static void launch_ln(const float* x, const float* g, const float* b,
                      void* y, int mode, int nrows) {
    ln_kernel<<<(nrows + 7) / 8, 256>>>(x, g, b, y, mode, nrows);
}

extern "C" void kernel_launch(void* const* d_in, const int* in_sizes, int n_in,
                              void* d_out, int out_size)
{
    const float* node_features = (const float*)d_in[0];
    const float* edge_features = (const float*)d_in[1];
    const float* edge_attr     = (const float*)d_in[2];
    const int*   neighbor_list = (const int*)d_in[3];
    const int*   num_valid     = (const int*)d_in[4];
    const float* W_edge = (const float*)d_in[5];
    const float* b_edge = (const float*)d_in[6];
    const float* W_node = (const float*)d_in[7];
    const float* b_node = (const float*)d_in[8];
    const float* W_msg  = (const float*)d_in[9];
    const float* b_msg  = (const float*)d_in[10];
    const float* W_qkv  = (const float*)d_in[11];
    const float* b_qkv  = (const float*)d_in[12];
    const float* W_out  = (const float*)d_in[13];
    const float* b_out  = (const float*)d_in[14];
    const float* g_attn = (const float*)d_in[15];
    const float* be_attn= (const float*)d_in[16];
    const float* g_fn   = (const float*)d_in[17];
    const float* be_fn  = (const float*)d_in[18];
    const float* g_fe   = (const float*)d_in[19];
    const float* be_fe  = (const float*)d_in[20];
    const float* Wn1 = (const float*)d_in[21];
    const float* bn1 = (const float*)d_in[22];
    const float* Wn2 = (const float*)d_in[23];
    const float* bn2 = (const float*)d_in[24];
    const float* We1 = (const float*)d_in[25];
    const float* be1 = (const float*)d_in[26];
    const float* We2 = (const float*)d_in[27];
    const float* be2 = (const float*)d_in[28];

    float *s_nh, *s_c, *s_nf1, *s_eh, *s_nh2, *s_big, *s_w;
    cudaGetSymbolAddress((void**)&s_nh,  S_nh);
    cudaGetSymbolAddress((void**)&s_c,   S_c);
    cudaGetSymbolAddress((void**)&s_nf1, S_nf1);
    cudaGetSymbolAddress((void**)&s_eh,  S_eh);
    cudaGetSymbolAddress((void**)&s_nh2, S_nh2);
    cudaGetSymbolAddress((void**)&s_big, S_big);
    cudaGetSymbolAddress((void**)&s_w,   S_w);

    cudaFuncSetAttribute(attn_kernel, cudaFuncAttributeMaxDynamicSharedMemorySize, ATTN_SMEM);

    float* out_node = (float*)d_out;
    float* out_edge = out_node + (long)N_ * H_;

    __half* h_nh  = (__half*)s_nh;
    __half* h_ea  = (__half*)s_big;
    __half* h_eh  = (__half*)s_eh;
    __half* h_nh2 = (__half*)s_nh2;
    __half* h_c   = (__half*)s_c;
    __half* h_qkv = (__half*)s_big;
    __half* h_hid = (__half*)s_big;
    float*  f_pre = s_eh;               // pre-resid edge_out (f32, after msg consumed)

    __half* wbase = (__half*)s_w;
    __half* tW_edge  = wbase;
    __half* tW_nodeC = wbase + 16384;
    __half* tW_nodeN = wbase + 32768;
    __half* tW_msgE  = wbase + 49152;
    __half* tW_msgN  = wbase + 65536;
    __half* tW_qkv   = wbase + 81920;
    __half* tW_out   = wbase + 131072;
    __half* tWn1     = wbase + 147456;
    __half* tWn2     = wbase + 180224;
    __half* tWe1     = wbase + 212992;
    __half* tWe2     = wbase + 245760;

    // 0) transpose+halve weights; halve edge_attr
    launch_T(W_edge,            tW_edge,  128, 128);
    launch_T(W_node,            tW_nodeC, 128, 128);
    launch_T(W_node + 128*128,  tW_nodeN, 128, 128);
    launch_T(W_msg,             tW_msgE,  128, 128);
    launch_T(W_msg + 128*128,   tW_msgN,  128, 128);
    launch_T(W_qkv,             tW_qkv,   128, 384);
    launch_T(W_out,             tW_out,   128, 128);
    launch_T(Wn1,               tWn1,     128, 256);
    launch_T(Wn2,               tWn2,     256, 128);
    launch_T(We1,               tWe1,     128, 256);
    launch_T(We2,               tWe2,     256, 128);
    launch_half(edge_attr, h_ea, (long)M_ * 128);

    // 1) node_hidden = LN(node_features) -> f16
    launch_ln(node_features, g_attn, be_attn, h_nh, 1, N_);
    // 2) edge_hidden = gelu(edge_attr @ W_edge + b) -> f16
    launch_gemm(h_ea, 128, nullptr, 0, tW_edge, nullptr, b_edge,
                nullptr, nullptr, 1, nullptr, h_eh, nullptr, M_, 128, 3);
    // 3a) center proj -> f32
    launch_gemm(h_nh, 128, nullptr, 0, tW_nodeC, nullptr, nullptr,
                nullptr, nullptr, 1, nullptr, s_c, nullptr, N_, 128, 0);
    // 3b) node_hid = gelu(nbr@WnodeN + center + b) -> f16 (gathered)
    launch_gemm(h_nh, 128, nullptr, 0, tW_nodeN, nullptr, b_node,
                neighbor_list, s_c, K_, nullptr, h_nh2, nullptr, M_, 128, 3);
    // 4) msg = gelu(eh@WmE + nh@WmN + b) -> f16 (in-place)
    launch_gemm(h_eh, 128, h_nh2, 128, tW_msgE, tW_msgN, b_msg,
                nullptr, nullptr, 1, nullptr, h_eh, nullptr, M_, 128, 3);
    // 5) qkv = msg @ W_qkv + b -> f16
    launch_gemm(h_eh, 128, nullptr, 0, tW_qkv, nullptr, b_qkv,
                nullptr, nullptr, 1, nullptr, h_qkv, nullptr, M_, 384, 2);
    // 6a) attention core -> ctx f16
    attn_kernel<<<N_, 256, ATTN_SMEM>>>(h_qkv, num_valid, h_nh2);
    // 6b) out-projection: out2 = f_pre (pre-resid), out = edge residual
    launch_gemm(h_nh2, 128, nullptr, 0, tW_out, nullptr, b_out,
                nullptr, nullptr, 1, edge_features, out_edge, f_pre, M_, 128, 0);
    // 6c) masked aggregation + node residual
    agg_kernel<<<N_, 128>>>(f_pre, node_features, num_valid, s_nf1);
    // 7) node FFN
    launch_ln(s_nf1, g_fn, be_fn, h_c, 1, N_);
    launch_gemm(h_c, 128, nullptr, 0, tWn1, nullptr, bn1,
                nullptr, nullptr, 1, nullptr, h_hid, nullptr, N_, 256, 3);
    launch_gemm(h_hid, 256, nullptr, 0, tWn2, nullptr, bn2,
                nullptr, nullptr, 1, s_nf1, out_node, nullptr, N_, 128, 0);
    // 8) edge FFN
    launch_ln(out_edge, g_fe, be_fe, h_nh2, 1, M_);
    launch_gemm(h_nh2, 128, nullptr, 0, tWe1, nullptr, be1,
                nullptr, nullptr, 1, nullptr, h_hid, nullptr, M_, 256, 3);
    launch_gemm(h_hid, 256, nullptr, 0, tWe2, nullptr, be2,
                nullptr, nullptr, 1, out_edge, out_edge, nullptr, M_, 128, 0);
}

// round 9
// speedup vs baseline: 1.6409x; 1.0610x over previous
#include <cuda_runtime.h>
#include <cuda_fp16.h>
#include <cstdint>

// Problem constants
#define N_  10000
#define K_  32
#define M_  (N_ * K_)      // 320000
#define H_  128

// ---------------- scratch (device globals) ------------------------------------
__device__ float S_nh [N_ * H_];
__device__ float S_c  [N_ * H_];
__device__ float S_nf1[N_ * H_];
__device__ float S_eh [M_ * H_];
__device__ float S_nh2[M_ * H_];
__device__ float S_big[M_ * 384];
__device__ float S_w  [139264];          // transposed half weights

__device__ __forceinline__ float gelu_t(float x) {
    float x3 = x * x * x;
    return 0.5f * x * (1.f + tanhf(0.7978845608028654f * (x + 0.044715f * x3)));
}

// ---------------- f32 -> f16 copy ----------------------------------------------
__global__ void __launch_bounds__(256) half_kernel(
    const float* __restrict__ src, __half* __restrict__ dst, long n4)
{
    long i = (long)blockIdx.x * 256 + threadIdx.x;
    if (i >= n4) return;
    float4 v = ((const float4*)src)[i];
    ((__half2*)dst)[i * 2 + 0] = __floats2half2_rn(v.x, v.y);
    ((__half2*)dst)[i * 2 + 1] = __floats2half2_rn(v.z, v.w);
}

// ---------------- transpose + halve: src[K][N] -> dst[N][K] ----------------------
__global__ void __launch_bounds__(256) transpose_half(
    const float* __restrict__ src, __half* __restrict__ dst, int Krows, int Ncols)
{
    __shared__ float tile[32][33];
    int bx = blockIdx.x * 32, by = blockIdx.y * 32;
    int x = threadIdx.x & 31, y4 = threadIdx.x >> 5;
#pragma unroll
    for (int j = 0; j < 4; j++) {
        int r = by + y4 + j * 8;
        if (r < Krows && bx + x < Ncols)
            tile[y4 + j * 8][x] = src[(long)r * Ncols + bx + x];
    }
    __syncthreads();
#pragma unroll
    for (int j = 0; j < 4; j++) {
        int n = bx + y4 + j * 8;
        if (n < Ncols && by + x < Krows)
            dst[(long)n * Krows + by + x] = __float2half_rn(tile[x][y4 + j * 8]);
    }
}

// ---------------- layernorm: warp-per-row (mode: 0=f32 out, 1=f16 out) -----------
__global__ void __launch_bounds__(256) ln_kernel(
    const float* __restrict__ x, const float* __restrict__ g,
    const float* __restrict__ b, void* __restrict__ y, int mode, int nrows)
{
    int row  = blockIdx.x * 8 + (threadIdx.x >> 5);
    if (row >= nrows) return;
    int lane = threadIdx.x & 31;
    long base = (long)row * 128 + lane * 4;
    float4 v = *(const float4*)(x + base);
    float s  = v.x + v.y + v.z + v.w;
    float s2 = v.x*v.x + v.y*v.y + v.z*v.z + v.w*v.w;
#pragma unroll
    for (int o = 16; o; o >>= 1) {
        s  += __shfl_xor_sync(0xffffffffu, s,  o);
        s2 += __shfl_xor_sync(0xffffffffu, s2, o);
    }
    float mean = s * (1.f / 128.f);
    float var  = s2 * (1.f / 128.f) - mean * mean;
    float r = rsqrtf(var + 1e-5f);
    float4 gv = *(const float4*)(g + lane * 4);
    float4 bv = *(const float4*)(b + lane * 4);
    float o0 = (v.x - mean) * r * gv.x + bv.x;
    float o1 = (v.y - mean) * r * gv.y + bv.y;
    float o2 = (v.z - mean) * r * gv.z + bv.z;
    float o3 = (v.w - mean) * r * gv.w + bv.w;
    if (mode) {
        __half2 h0 = __floats2half2_rn(o0, o1);
        __half2 h1 = __floats2half2_rn(o2, o3);
        uint2 pk = make_uint2(*(uint32_t*)&h0, *(uint32_t*)&h1);
        *(uint2*)((__half*)y + base) = pk;
    } else {
        *(float4*)((float*)y + base) = make_float4(o0, o1, o2, o3);
    }
}

// ---------------- pipelined fp16 tensor GEMM (R5/R8-proven, unchanged) -----------
#define BK 32
#define AS_BYTES 10240
#define WS_OFF   20480
#define GEMM_SMEM 40960

__device__ __forceinline__ void cp16(uint32_t dst, const void* src, int sz) {
    asm volatile("cp.async.cg.shared.global [%0], [%1], 16, %2;"
                 :: "r"(dst), "l"(src), "r"(sz));
}

__global__ void __launch_bounds__(256, 2) gemm_h(
    const __half* __restrict__ A,  int kdA,
    const __half* __restrict__ A2, int kdA2,
    const __half* __restrict__ Wt, const __half* __restrict__ Wt2,
    const float* __restrict__ bias,
    const int*   __restrict__ gather,
    const float* __restrict__ rowvec, int rowdiv,
    const float* __restrict__ resid,
    void* __restrict__ out, float* __restrict__ out2,
    int M, int ncols, int flags)
{
    extern __shared__ __half smh[];
    uint32_t smb = (uint32_t)__cvta_generic_to_shared(smh);

    int tid  = threadIdx.x;
    int lane = tid & 31;
    int wid  = tid >> 5;
    int warp_m = wid >> 2;
    int warp_n = wid & 3;
    int qr = lane >> 2;
    int qc = lane & 3;
    int row0 = blockIdx.x * 128;
    int cb   = blockIdx.y * 128;

    int kc = tid & 3;
    int lrow0 = tid >> 2;
    long arow_[2]; int pr_[2];
#pragma unroll
    for (int i = 0; i < 2; i++) {
        int gr = row0 + lrow0 + 64 * i;
        pr_[i] = (gr < M) ? 16 : 0;
        arow_[i] = (gr < M) ? (gather ? (long)gather[gr] : (long)gr) : 0;
    }
    int t1 = kdA / BK;
    int nt = t1 + (A2 ? kdA2 / BK : 0);

#define ISSUE(T) do {                                                           \
        int _t = (T); int _p = (_t >= t1);                                      \
        const __half* _Ap = _p ? A2 : A;                                        \
        const __half* _Wp = _p ? Wt2 : Wt;                                      \
        int _kd = _p ? kdA2 : kdA;                                              \
        int _k0 = (_p ? _t - t1 : _t) * BK;                                     \
        uint32_t _ab = smb + (_t & 1) * AS_BYTES;                               \
        uint32_t _wb = smb + WS_OFF + (_t & 1) * AS_BYTES;                      \
        _Pragma("unroll")                                                       \
        for (int _i = 0; _i < 2; _i++)                                          \
            cp16(_ab + (lrow0 + 64 * _i) * 80 + kc * 16,                        \
                 _Ap + arow_[_i] * _kd + _k0 + kc * 8, pr_[_i]);                \
        _Pragma("unroll")                                                       \
        for (int _i = 0; _i < 2; _i++)                                          \
            cp16(_wb + (lrow0 + 64 * _i) * 80 + kc * 16,                        \
                 _Wp + (long)(cb + lrow0 + 64 * _i) * _kd + _k0 + kc * 8, 16);  \
        asm volatile("cp.async.commit_group;" ::: "memory");                    \
    } while (0)

    float acc[4][4][4];
#pragma unroll
    for (int i = 0; i < 4; i++)
#pragma unroll
        for (int j = 0; j < 4; j++)
#pragma unroll
            for (int c = 0; c < 4; c++) acc[i][j][c] = 0.f;

    ISSUE(0);
    for (int t = 0; t < nt; t++) {
        int cur = t & 1;
        if (t + 1 < nt) {
            ISSUE(t + 1);
            asm volatile("cp.async.wait_group 1;" ::: "memory");
        } else {
            asm volatile("cp.async.wait_group 0;" ::: "memory");
        }
        __syncthreads();

        const __half* Asf = smh + cur * (AS_BYTES / 2) + (warp_m * 64) * 40;
        const __half* Wsf = smh + (WS_OFF / 2) + cur * (AS_BYTES / 2) + (warp_n * 32) * 40;
#pragma unroll
        for (int ks = 0; ks < 2; ks++) {
            int k16 = ks * 16;
            uint32_t af[4][4];
#pragma unroll
            for (int mt = 0; mt < 4; mt++) {
                const __half* p = Asf + (mt * 16 + qr) * 40 + k16 + qc * 2;
                af[mt][0] = *(const uint32_t*)(p);
                af[mt][1] = *(const uint32_t*)(p + 8 * 40);
                af[mt][2] = *(const uint32_t*)(p + 8);
                af[mt][3] = *(const uint32_t*)(p + 8 * 40 + 8);
            }
            uint32_t bf[4][2];
#pragma unroll
            for (int nt2 = 0; nt2 < 4; nt2++) {
                const __half* p = Wsf + (nt2 * 8 + qr) * 40 + k16 + qc * 2;
                bf[nt2][0] = *(const uint32_t*)(p);
                bf[nt2][1] = *(const uint32_t*)(p + 8);
            }
#pragma unroll
            for (int mt = 0; mt < 4; mt++)
#pragma unroll
                for (int nt2 = 0; nt2 < 4; nt2++) {
                    asm volatile(
                        "mma.sync.aligned.m16n8k16.row.col.f32.f16.f16.f32 "
                        "{%0,%1,%2,%3}, {%4,%5,%6,%7}, {%8,%9}, {%0,%1,%2,%3};"
                        : "+f"(acc[mt][nt2][0]), "+f"(acc[mt][nt2][1]),
                          "+f"(acc[mt][nt2][2]), "+f"(acc[mt][nt2][3])
                        : "r"(af[mt][0]), "r"(af[mt][1]),
                          "r"(af[mt][2]), "r"(af[mt][3]),
                          "r"(bf[nt2][0]), "r"(bf[nt2][1]));
                }
        }
        __syncthreads();
    }
#undef ISSUE

    int gelu = flags & 1, halfout = flags & 2;
#pragma unroll
    for (int mt = 0; mt < 4; mt++) {
#pragma unroll
        for (int hh = 0; hh < 2; hh++) {
            int gr = row0 + warp_m * 64 + mt * 16 + hh * 8 + qr;
            if (gr >= M) continue;
            const float* rv = rowvec ? rowvec + (long)(gr / rowdiv) * 128 : nullptr;
#pragma unroll
            for (int nt2 = 0; nt2 < 4; nt2++) {
                int c = cb + warp_n * 32 + nt2 * 8 + qc * 2;
                float v0 = acc[mt][nt2][hh * 2 + 0];
                float v1 = acc[mt][nt2][hh * 2 + 1];
                if (bias) { v0 += bias[c];  v1 += bias[c + 1]; }
                if (rv)   { v0 += rv[c];    v1 += rv[c + 1]; }
                if (gelu) { v0 = gelu_t(v0); v1 = gelu_t(v1); }
                long oidx = (long)gr * ncols + c;
                if (halfout) {
                    *(__half2*)((__half*)out + oidx) = __floats2half2_rn(v0, v1);
                } else {
                    if (out2) *(float2*)(out2 + oidx) = make_float2(v0, v1);
                    if (resid) {
                        float2 r2 = *(const float2*)(resid + oidx);
                        v0 += r2.x; v1 += r2.y;
                    }
                    *(float2*)((float*)out + oidx) = make_float2(v0, v1);
                }
            }
        }
    }
}

// ---------------- fused attention + out-proj + residual + aggregation -----------
// Per CTA: 2 nodes. qkv f16 -> smem; attention in regs; ctx f16 smem;
// outproj via mma against smem W_out; epilogue: +b_out, masked shfl-agg -> node1,
// +edge_features -> out_edge.
#define FAT_SMEM 102400
__device__ __forceinline__ void cvt16(float* o, const __half* p) {
    uint4 a = *(const uint4*)p, b = *(const uint4*)(p + 8);
    const __half2* ha = (const __half2*)&a;
    const __half2* hb = (const __half2*)&b;
#pragma unroll
    for (int i = 0; i < 4; i++) {
        float2 f = __half22float2(ha[i]);
        o[i * 2] = f.x; o[i * 2 + 1] = f.y;
    }
#pragma unroll
    for (int i = 0; i < 4; i++) {
        float2 f = __half22float2(hb[i]);
        o[8 + i * 2] = f.x; o[8 + i * 2 + 1] = f.y;
    }
}

__global__ void __launch_bounds__(256) fused_attn(
    const __half* __restrict__ qkv, const __half* __restrict__ wout,
    const float* __restrict__ b_out, const int* __restrict__ num_valid,
    const float* __restrict__ edge_feat, const float* __restrict__ node_feat,
    float* __restrict__ out_edge, float* __restrict__ node1)
{
    extern __shared__ __half sh[];
    __half* qkvS = sh;                     // 24576 halves: [64 rows][384]
    __half* ctxS = sh + 24576;             // [64][136]
    __half* woutS = sh + 33280;            // [128][136]
    float*  sAgg  = (float*)(sh + 50688);  // [2][128]

    int tid = threadIdx.x;
    int n0 = blockIdx.x * 2;

    sAgg[tid] = 0.f;

    // load qkv for 2 nodes (contiguous)
    const uint4* src = (const uint4*)(qkv + (long)n0 * 32 * 384);
    uint4* dq = (uint4*)qkvS;
#pragma unroll
    for (int i = 0; i < 12; i++) dq[tid + i * 256] = src[tid + i * 256];

    // load W_out [n][K=128] -> padded stride 136
#pragma unroll
    for (int i = 0; i < 8; i++) {
        int c = tid + i * 256;
        int nn = c >> 4, k8 = c & 15;
        *(uint4*)(woutS + nn * 136 + k8 * 8) = *(const uint4*)(wout + nn * 128 + k8 * 8);
    }
    __syncthreads();

    int nv0 = num_valid[n0], nv1 = num_valid[n0 + 1];

    // --- attention: 512 (node,head,q) items, 2 per thread ---
    for (int it = tid; it < 512; it += 256) {
        int node = it >> 8;
        int head = (it >> 5) & 7;
        int q    = it & 31;
        int nv   = node ? nv1 : nv0;
        const __half* base = qkvS + (node * 32) * 384 + head * 16;
        float qv[16];
        cvt16(qv, base + q * 384);
        float s[32];
#pragma unroll
        for (int j = 0; j < 32; j++) {
            float kv[16];
            cvt16(kv, base + j * 384 + 128);
            float a = 0.f;
#pragma unroll
            for (int d = 0; d < 16; d++) a += qv[d] * kv[d];
            s[j] = a * 0.25f;
        }
        float m = -1e30f;
#pragma unroll
        for (int j = 0; j < 32; j++) if (j < nv && s[j] > m) m = s[j];
        float sum = 0.f;
#pragma unroll
        for (int j = 0; j < 32; j++) {
            float p = (j < nv) ? __expf(s[j] - m) : 0.f;
            s[j] = p; sum += p;
        }
        float inv = 1.f / sum;
        float ctx[16];
#pragma unroll
        for (int d = 0; d < 16; d++) ctx[d] = 0.f;
#pragma unroll
        for (int j = 0; j < 32; j++) {
            float p = s[j] * inv;
            float vv[16];
            cvt16(vv, base + j * 384 + 256);
#pragma unroll
            for (int d = 0; d < 16; d++) ctx[d] += p * vv[d];
        }
        uint4 o0, o1; __half2 h;
        h = __floats2half2_rn(ctx[0],  ctx[1]);  o0.x = *(uint32_t*)&h;
        h = __floats2half2_rn(ctx[2],  ctx[3]);  o0.y = *(uint32_t*)&h;
        h = __floats2half2_rn(ctx[4],  ctx[5]);  o0.z = *(uint32_t*)&h;
        h = __floats2half2_rn(ctx[6],  ctx[7]);  o0.w = *(uint32_t*)&h;
        h = __floats2half2_rn(ctx[8],  ctx[9]);  o1.x = *(uint32_t*)&h;
        h = __floats2half2_rn(ctx[10], ctx[11]); o1.y = *(uint32_t*)&h;
        h = __floats2half2_rn(ctx[12], ctx[13]); o1.z = *(uint32_t*)&h;
        h = __floats2half2_rn(ctx[14], ctx[15]); o1.w = *(uint32_t*)&h;
        __half* cd = ctxS + (node * 32 + q) * 136 + head * 16;
        *(uint4*)cd = o0;
        *(uint4*)(cd + 8) = o1;
    }
    __syncthreads();

    // --- out-projection: 64 x 128 = ctx(64x128) @ Wout^T via mma ---
    int lane = tid & 31, wid = tid >> 5;
    int warp_m = wid >> 2, warp_n = wid & 3;
    int qr = lane >> 2, qc = lane & 3;
    float acc[2][4][4];
#pragma unroll
    for (int i = 0; i < 2; i++)
#pragma unroll
        for (int j = 0; j < 4; j++)
#pragma unroll
            for (int c = 0; c < 4; c++) acc[i][j][c] = 0.f;

#pragma unroll
    for (int ks = 0; ks < 8; ks++) {
        int k16 = ks * 16;
        uint32_t af[2][4];
#pragma unroll
        for (int mt = 0; mt < 2; mt++) {
            const __half* p = ctxS + (warp_m * 32 + mt * 16 + qr) * 136 + k16 + qc * 2;
            af[mt][0] = *(const uint32_t*)(p);
            af[mt][1] = *(const uint32_t*)(p + 8 * 136);
            af[mt][2] = *(const uint32_t*)(p + 8);
            af[mt][3] = *(const uint32_t*)(p + 8 * 136 + 8);
        }
        uint32_t bf[4][2];
#pragma unroll
        for (int nt2 = 0; nt2 < 4; nt2++) {
            const __half* p = woutS + (warp_n * 32 + nt2 * 8 + qr) * 136 + k16 + qc * 2;
            bf[nt2][0] = *(const uint32_t*)(p);
            bf[nt2][1] = *(const uint32_t*)(p + 8);
        }
#pragma unroll
        for (int mt = 0; mt < 2; mt++)
#pragma unroll
            for (int nt2 = 0; nt2 < 4; nt2++) {
                asm volatile(
                    "mma.sync.aligned.m16n8k16.row.col.f32.f16.f16.f32 "
                    "{%0,%1,%2,%3}, {%4,%5,%6,%7}, {%8,%9}, {%0,%1,%2,%3};"
                    : "+f"(acc[mt][nt2][0]), "+f"(acc[mt][nt2][1]),
                      "+f"(acc[mt][nt2][2]), "+f"(acc[mt][nt2][3])
                    : "r"(af[mt][0]), "r"(af[mt][1]),
                      "r"(af[mt][2]), "r"(af[mt][3]),
                      "r"(bf[nt2][0]), "r"(bf[nt2][1]));
            }
    }

    // --- epilogue: bias, masked shfl-agg, edge residual ---
#pragma unroll
    for (int mt = 0; mt < 2; mt++) {
#pragma unroll
        for (int hh = 0; hh < 2; hh++) {
            int lr = warp_m * 32 + mt * 16 + hh * 8 + qr;   // 0..63
            int node = lr >> 5, kk = lr & 31;
            int nv = node ? nv1 : nv0;
            bool valid = kk < nv;
            long erow = ((long)(n0 + node) * 32 + kk) * 128;
#pragma unroll
            for (int nt2 = 0; nt2 < 4; nt2++) {
                int c = warp_n * 32 + nt2 * 8 + qc * 2;
                float v0 = acc[mt][nt2][hh * 2 + 0] + b_out[c];
                float v1 = acc[mt][nt2][hh * 2 + 1] + b_out[c + 1];
                float m0 = valid ? v0 : 0.f;
                float m1 = valid ? v1 : 0.f;
#pragma unroll
                for (int off = 4; off <= 16; off <<= 1) {
                    m0 += __shfl_xor_sync(0xffffffffu, m0, off);
                    m1 += __shfl_xor_sync(0xffffffffu, m1, off);
                }
                if (qr == 0) {
                    atomicAdd(&sAgg[node * 128 + c], m0);
                    atomicAdd(&sAgg[node * 128 + c + 1], m1);
                }
                float2 r2 = *(const float2*)(edge_feat + erow + c);
                *(float2*)(out_edge + erow + c) = make_float2(v0 + r2.x, v1 + r2.y);
            }
        }
    }
    __syncthreads();
    {
        int node = tid >> 7, c = tid & 127;
        long nidx = (long)(n0 + node) * 128 + c;
        node1[nidx] = sAgg[node * 128 + c] + node_feat[nidx];
    }
}

// ---------------- driver -----------------------------------------------------------
static void launch_gemm(const __half* A, int kdA, const __half* A2, int kdA2,
                        const __half* Wt, const __half* Wt2, const float* bias,
                        const int* gather, const float* rowvec, int rowdiv,
                        const float* resid, void* out, float* out2,
                        int M, int ncols, int flags)
{
    dim3 g((M + 127) / 128, ncols / 128);
    gemm_h<<<g, 256, GEMM_SMEM>>>(A, kdA, A2, kdA2, Wt, Wt2, bias, gather,
                                  rowvec, rowdiv, resid, out, out2, M, ncols, flags);
}
static void launch_T(const float* src, __half* dst, int K, int N) {
    dim3 g((N + 31) / 32, (K + 31) / 32);
    transpose_half<<<g, 256>>>(src, dst, K, N);
}
static void launch_half(const float* src, __half* dst, long n) {
    long n4 = n / 4;
    half_kernel<<<(unsigned)((n4 + 255) / 256), 256>>>(src, dst, n4);
}
static void launch_ln(const float* x, const float* g, const float* b,
                      void* y, int mode, int nrows) {
    ln_kernel<<<(nrows + 7) / 8, 256>>>(x, g, b, y, mode, nrows);
}

extern "C" void kernel_launch(void* const* d_in, const int* in_sizes, int n_in,
                              void* d_out, int out_size)
{
    const float* node_features = (const float*)d_in[0];
    const float* edge_features = (const float*)d_in[1];
    const float* edge_attr     = (const float*)d_in[2];
    const int*   neighbor_list = (const int*)d_in[3];
    const int*   num_valid     = (const int*)d_in[4];
    const float* W_edge = (const float*)d_in[5];
    const float* b_edge = (const float*)d_in[6];
    const float* W_node = (const float*)d_in[7];
    const float* b_node = (const float*)d_in[8];
    const float* W_msg  = (const float*)d_in[9];
    const float* b_msg  = (const float*)d_in[10];
    const float* W_qkv  = (const float*)d_in[11];
    const float* b_qkv  = (const float*)d_in[12];
    const float* W_out  = (const float*)d_in[13];
    const float* b_out  = (const float*)d_in[14];
    const float* g_attn = (const float*)d_in[15];
    const float* be_attn= (const float*)d_in[16];
    const float* g_fn   = (const float*)d_in[17];
    const float* be_fn  = (const float*)d_in[18];
    const float* g_fe   = (const float*)d_in[19];
    const float* be_fe  = (const float*)d_in[20];
    const float* Wn1 = (const float*)d_in[21];
    const float* bn1 = (const float*)d_in[22];
    const float* Wn2 = (const float*)d_in[23];
    const float* bn2 = (const float*)d_in[24];
    const float* We1 = (const float*)d_in[25];
    const float* be1 = (const float*)d_in[26];
    const float* We2 = (const float*)d_in[27];
    const float* be2 = (const float*)d_in[28];

    float *s_nh, *s_c, *s_nf1, *s_eh, *s_nh2, *s_big, *s_w;
    cudaGetSymbolAddress((void**)&s_nh,  S_nh);
    cudaGetSymbolAddress((void**)&s_c,   S_c);
    cudaGetSymbolAddress((void**)&s_nf1, S_nf1);
    cudaGetSymbolAddress((void**)&s_eh,  S_eh);
    cudaGetSymbolAddress((void**)&s_nh2, S_nh2);
    cudaGetSymbolAddress((void**)&s_big, S_big);
    cudaGetSymbolAddress((void**)&s_w,   S_w);

    cudaFuncSetAttribute(fused_attn, cudaFuncAttributeMaxDynamicSharedMemorySize, FAT_SMEM);

    float* out_node = (float*)d_out;
    float* out_edge = out_node + (long)N_ * H_;

    __half* h_nh  = (__half*)s_nh;
    __half* h_ea  = (__half*)s_big;
    __half* h_eh  = (__half*)s_eh;
    __half* h_nh2 = (__half*)s_nh2;
    __half* h_c   = (__half*)s_c;
    __half* h_qkv = (__half*)s_big;
    __half* h_hid = (__half*)s_big;

    __half* wbase = (__half*)s_w;
    __half* tW_edge  = wbase;
    __half* tW_nodeC = wbase + 16384;
    __half* tW_nodeN = wbase + 32768;
    __half* tW_msgE  = wbase + 49152;
    __half* tW_msgN  = wbase + 65536;
    __half* tW_qkv   = wbase + 81920;
    __half* tW_out   = wbase + 131072;
    __half* tWn1     = wbase + 147456;
    __half* tWn2     = wbase + 180224;
    __half* tWe1     = wbase + 212992;
    __half* tWe2     = wbase + 245760;

    // 0) transpose+halve weights; halve edge_attr
    launch_T(W_edge,            tW_edge,  128, 128);
    launch_T(W_node,            tW_nodeC, 128, 128);
    launch_T(W_node + 128*128,  tW_nodeN, 128, 128);
    launch_T(W_msg,             tW_msgE,  128, 128);
    launch_T(W_msg + 128*128,   tW_msgN,  128, 128);
    launch_T(W_qkv,             tW_qkv,   128, 384);
    launch_T(W_out,             tW_out,   128, 128);
    launch_T(Wn1,               tWn1,     128, 256);
    launch_T(Wn2,               tWn2,     256, 128);
    launch_T(We1,               tWe1,     128, 256);
    launch_T(We2,               tWe2,     256, 128);
    launch_half(edge_attr, h_ea, (long)M_ * 128);

    // 1) node_hidden = LN(node_features) -> f16
    launch_ln(node_features, g_attn, be_attn, h_nh, 1, N_);
    // 2) edge_hidden = gelu(edge_attr @ W_edge + b) -> f16
    launch_gemm(h_ea, 128, nullptr, 0, tW_edge, nullptr, b_edge,
                nullptr, nullptr, 1, nullptr, h_eh, nullptr, M_, 128, 3);
    // 3a) center proj -> f32
    launch_gemm(h_nh, 128, nullptr, 0, tW_nodeC, nullptr, nullptr,
                nullptr, nullptr, 1, nullptr, s_c, nullptr, N_, 128, 0);
    // 3b) node_hid = gelu(nbr@WnodeN + center + b) -> f16 (gathered)
    launch_gemm(h_nh, 128, nullptr, 0, tW_nodeN, nullptr, b_node,
                neighbor_list, s_c, K_, nullptr, h_nh2, nullptr, M_, 128, 3);
    // 4) msg = gelu(eh@WmE + nh@WmN + b) -> f16 (in-place)
    launch_gemm(h_eh, 128, h_nh2, 128, tW_msgE, tW_msgN, b_msg,
                nullptr, nullptr, 1, nullptr, h_eh, nullptr, M_, 128, 3);
    // 5) qkv = msg @ W_qkv + b -> f16
    launch_gemm(h_eh, 128, nullptr, 0, tW_qkv, nullptr, b_qkv,
                nullptr, nullptr, 1, nullptr, h_qkv, nullptr, M_, 384, 2);
    // 6) fused: attention + out-proj + edge residual + masked aggregation
    fused_attn<<<N_ / 2, 256, FAT_SMEM>>>(h_qkv, tW_out, b_out, num_valid,
                                          edge_features, node_features,
                                          out_edge, s_nf1);
    // 7) node FFN
    launch_ln(s_nf1, g_fn, be_fn, h_c, 1, N_);
    launch_gemm(h_c, 128, nullptr, 0, tWn1, nullptr, bn1,
                nullptr, nullptr, 1, nullptr, h_hid, nullptr, N_, 256, 3);
    launch_gemm(h_hid, 256, nullptr, 0, tWn2, nullptr, bn2,
                nullptr, nullptr, 1, s_nf1, out_node, nullptr, N_, 128, 0);
    // 8) edge FFN
    launch_ln(out_edge, g_fe, be_fe, h_nh2, 1, M_);
    launch_gemm(h_nh2, 128, nullptr, 0, tWe1, nullptr, be1,
                nullptr, nullptr, 1, nullptr, h_hid, nullptr, M_, 256, 3);
    launch_gemm(h_hid, 256, nullptr, 0, tWe2, nullptr, be2,
                nullptr, nullptr, 1, out_edge, out_edge, nullptr, M_, 128, 0);
}